// round 15
// baseline (speedup 1.0000x reference)
#include <cuda_runtime.h>
#include <cuda_fp16.h>
#include <math.h>
#include <stdint.h>

#define BB   2
#define NN   2048
#define DD   2048
#define HH   16
#define DHH  128
#define MTOT (BB*NN)
#define SCALE 0.08838834764831845f

// ---------------- device scratch ----------------
__device__ __half g_Xh [(size_t)MTOT*DD];
__device__ __half g_Wqh[(size_t)DD*DD];       // native [k][n] fp16
__device__ __half g_Wkh[(size_t)DD*DD];
__device__ __half g_Wvh[(size_t)DD*DD];
__device__ __half g_Woh[(size_t)DD*DD];
__device__ __half g_Qp [(size_t)BB*HH*NN*DHH]; // fp16 pre-rope
__device__ __half g_Kp [(size_t)BB*HH*NN*DHH];
__device__ __half g_Qh [(size_t)BB*HH*NN*DHH]; // fp16 post-rope (+scale)
__device__ __half g_Kh [(size_t)BB*HH*NN*DHH];
__device__ __half g_Vh [(size_t)BB*HH*NN*DHH];
__device__ __half g_Oh [(size_t)MTOT*DD];      // gated merged heads
__device__ float  g_gate[(size_t)MTOT*HH];
__device__ float4 g_cs [(size_t)NN*64];        // (cos1,sin1,cos2,sin2)

// ================= asm helpers =================
__device__ __forceinline__ uint32_t smem_u32(const void* p) {
    uint32_t a;
    asm("{ .reg .u64 t; cvta.to.shared.u64 t, %1; cvt.u32.u64 %0, t; }" : "=r"(a) : "l"(p));
    return a;
}
__device__ __forceinline__ void cp16(uint32_t dst, const void* src) {
    asm volatile("cp.async.cg.shared.global [%0], [%1], 16;" :: "r"(dst), "l"(src));
}
__device__ __forceinline__ void cp_commit() { asm volatile("cp.async.commit_group;" ::: "memory"); }
template<int N> __device__ __forceinline__ void cp_wait() {
    asm volatile("cp.async.wait_group %0;" :: "n"(N) : "memory");
}
__device__ __forceinline__ void ldsm4(uint32_t* r, uint32_t a) {
    asm volatile("ldmatrix.sync.aligned.m8n8.x4.shared.b16 {%0,%1,%2,%3}, [%4];"
                 : "=r"(r[0]), "=r"(r[1]), "=r"(r[2]), "=r"(r[3]) : "r"(a));
}
__device__ __forceinline__ void ldsm4t(uint32_t* r, uint32_t a) {
    asm volatile("ldmatrix.sync.aligned.m8n8.x4.trans.shared.b16 {%0,%1,%2,%3}, [%4];"
                 : "=r"(r[0]), "=r"(r[1]), "=r"(r[2]), "=r"(r[3]) : "r"(a));
}
__device__ __forceinline__ void mma_f16(float* c, const uint32_t* a, uint32_t b0, uint32_t b1) {
    asm volatile("mma.sync.aligned.m16n8k16.row.col.f32.f16.f16.f32 "
                 "{%0,%1,%2,%3}, {%4,%5,%6,%7}, {%8,%9}, {%0,%1,%2,%3};"
                 : "+f"(c[0]), "+f"(c[1]), "+f"(c[2]), "+f"(c[3])
                 : "r"(a[0]), "r"(a[1]), "r"(a[2]), "r"(a[3]), "r"(b0), "r"(b1));
}
__device__ __forceinline__ uint32_t packh2(float lo, float hi) {
    __half2 h = __floats2half2_rn(lo, hi);
    return *reinterpret_cast<uint32_t*>(&h);
}

// ================= fused conversion: x + 4 weights -> fp16 ==================
#define XN  ((size_t)MTOT*DD)
#define WN  ((size_t)DD*DD)
__global__ void conv_all_kernel(const float* __restrict__ x,
                                const float* __restrict__ Wq,
                                const float* __restrict__ Wk,
                                const float* __restrict__ Wv,
                                const float* __restrict__ Wo)
{
    size_t i = (size_t)(blockIdx.x * blockDim.x + threadIdx.x) * 8;
    const float* src; __half* dst;
    if      (i < XN)        { src = x  + i;               dst = g_Xh  + i; }
    else if (i < XN + WN)   { src = Wq + (i - XN);        dst = g_Wqh + (i - XN); }
    else if (i < XN + 2*WN) { src = Wk + (i - XN - WN);   dst = g_Wkh + (i - XN - WN); }
    else if (i < XN + 3*WN) { src = Wv + (i - XN - 2*WN); dst = g_Wvh + (i - XN - 2*WN); }
    else                    { src = Wo + (i - XN - 3*WN); dst = g_Woh + (i - XN - 3*WN); }
    float4 v0 = *(const float4*)(src);
    float4 v1 = *(const float4*)(src + 4);
    uint4 o;
    o.x = packh2(v0.x, v0.y); o.y = packh2(v0.z, v0.w);
    o.z = packh2(v1.x, v1.y); o.w = packh2(v1.z, v1.w);
    *(uint4*)(dst) = o;
}

// cos/sin table
__global__ void cs_table_kernel(const float* __restrict__ freqs)
{
    int idx = blockIdx.x * blockDim.x + threadIdx.x;
    int n = idx >> 6, half = idx & 63;
    float f1 = freqs[(size_t)n * DHH + half];
    float f2 = freqs[(size_t)n * DHH + half + 64];
    g_cs[idx] = make_float4(cosf(f1), sinf(f1), cosf(f2), sinf(f2));
}

// ================= fused QKV GEMM: 3-stage pipeline, wait<1> ================
#define PADH 72                        // A row stride (halves)
#define PADB 136                       // B row stride (halves)
#define A_STH (128 * PADH)             // 9216 halves
#define B_STH (64 * PADB)              // 8704 halves
#define QKV_STG 3
#define OFFB (QKV_STG * A_STH)
#define QKV_SMEM ((QKV_STG * A_STH + 3 * QKV_STG * B_STH) * 2)   // 211,968 B

__device__ __forceinline__ void qkv_load(uint32_t sb, int s, int row0, int col0,
                                         int k0, int tid)
{
    {   // A: 128 rows x 64 halves
        int r = tid >> 1, hh = (tid & 1) * 32;
        uint32_t dst = sb + (uint32_t)(s * A_STH + r * PADH + hh) * 2;
        const __half* src = g_Xh + (size_t)(row0 + r) * DD + k0 + hh;
#pragma unroll
        for (int j = 0; j < 4; j++) cp16(dst + j * 16, src + j * 8);
    }
    {   // B: 64 k-rows x 128 n, three weights, native layout
        int r = tid >> 2, p = (tid & 3) * 32;
        const __half* Ws[3] = {g_Wqh, g_Wkh, g_Wvh};
#pragma unroll
        for (int w = 0; w < 3; w++) {
            uint32_t dst = sb + (uint32_t)(OFFB + (w * QKV_STG + s) * B_STH + r * PADB + p) * 2;
            const __half* src = Ws[w] + (size_t)(k0 + r) * DD + col0 + p;
#pragma unroll
            for (int j = 0; j < 4; j++) cp16(dst + j * 16, src + j * 8);
        }
    }
}

__global__ __launch_bounds__(256, 1)
void qkv_h_kernel()
{
    extern __shared__ char smraw[];
    uint32_t sb = smem_u32(smraw);
    const int tid = threadIdx.x;
    const int wid = tid >> 5, lane = tid & 31;
    const int g = lane >> 2, tg = lane & 3;
    const int wm = wid & 1, wn = wid >> 1;
    const int row0 = blockIdx.y * 128;
    const int col0 = blockIdx.x * 128;
    const int lr = lane & 7, lb3 = (lane >> 3) & 1, lb4 = lane >> 4;

    float c[3][4][4][4];
#pragma unroll
    for (int t = 0; t < 3; t++)
#pragma unroll
        for (int mf = 0; mf < 4; mf++)
#pragma unroll
            for (int nf = 0; nf < 4; nf++)
#pragma unroll
                for (int r = 0; r < 4; r++) c[t][mf][nf][r] = 0.f;

    qkv_load(sb, 0, row0, col0, 0, tid);
    cp_commit();
    qkv_load(sb, 1, row0, col0, 64, tid);
    cp_commit();

    for (int i = 0; i < 32; i++) {
        if (i + 2 < 32) cp_wait<1>();
        else            cp_wait<0>();
        __syncthreads();
        if (i + 2 < 32) {
            qkv_load(sb, (i + 2) % QKV_STG, row0, col0, (i + 2) * 64, tid);
            cp_commit();
        }
        int s = i % QKV_STG;
        uint32_t Ab = sb + (uint32_t)(s * A_STH) * 2;
#pragma unroll
        for (int kk = 0; kk < 4; kk++) {
            uint32_t af[4][4];
#pragma unroll
            for (int mf = 0; mf < 4; mf++)
                ldsm4(af[mf], Ab + (uint32_t)((wm * 64 + mf * 16 + lb3 * 8 + lr) * PADH
                                              + kk * 16 + lb4 * 8) * 2);
#pragma unroll
            for (int w = 0; w < 3; w++) {
                uint32_t Bb = sb + (uint32_t)(OFFB + (w * QKV_STG + s) * B_STH) * 2;
#pragma unroll
                for (int np = 0; np < 2; np++) {
                    uint32_t bf[4];
                    ldsm4t(bf, Bb + (uint32_t)((kk * 16 + lb3 * 8 + lr) * PADB
                                               + wn * 32 + np * 16 + lb4 * 8) * 2);
#pragma unroll
                    for (int mf = 0; mf < 4; mf++) {
                        mma_f16(c[w][mf][np * 2],     af[mf], bf[0], bf[1]);
                        mma_f16(c[w][mf][np * 2 + 1], af[mf], bf[2], bf[3]);
                    }
                }
            }
        }
    }

    const int h = blockIdx.x;
#pragma unroll
    for (int mf = 0; mf < 4; mf++) {
#pragma unroll
        for (int nf = 0; nf < 4; nf++) {
            int dh = wn * 32 + nf * 8 + tg * 2;
#pragma unroll
            for (int hf = 0; hf < 2; hf++) {
                int m = row0 + wm * 64 + mf * 16 + g + hf * 8;
                int b = m >> 11, n = m & (NN - 1);
                size_t off = ((size_t)(b * HH + h) * NN + n) * DHH + dh;
                *(uint32_t*)(g_Qp + off) = packh2(c[0][mf][nf][hf * 2], c[0][mf][nf][hf * 2 + 1]);
                *(uint32_t*)(g_Kp + off) = packh2(c[1][mf][nf][hf * 2], c[1][mf][nf][hf * 2 + 1]);
                *(uint32_t*)(g_Vh + off) = packh2(c[2][mf][nf][hf * 2], c[2][mf][nf][hf * 2 + 1]);
            }
        }
    }
}

// ================= output projection: 3-stage pipeline, wait<1> =============
#define O_STG 3
#define OOFFB (O_STG * A_STH)
#define OGEMM_SMEM ((O_STG * A_STH + O_STG * B_STH) * 2)   // 107,520 B

__device__ __forceinline__ void o_load(uint32_t sb, int s, int row0, int col0,
                                       int k0, int tid)
{
    {
        int r = tid >> 1, hh = (tid & 1) * 32;
        uint32_t dst = sb + (uint32_t)(s * A_STH + r * PADH + hh) * 2;
        const __half* src = g_Oh + (size_t)(row0 + r) * DD + k0 + hh;
#pragma unroll
        for (int j = 0; j < 4; j++) cp16(dst + j * 16, src + j * 8);
    }
    {
        int r = tid >> 2, p = (tid & 3) * 32;
        uint32_t dst = sb + (uint32_t)(OOFFB + s * B_STH + r * PADB + p) * 2;
        const __half* src = g_Woh + (size_t)(k0 + r) * DD + col0 + p;
#pragma unroll
        for (int j = 0; j < 4; j++) cp16(dst + j * 16, src + j * 8);
    }
}

__global__ __launch_bounds__(256, 1)
void gemm_oh_kernel(float* __restrict__ out)
{
    extern __shared__ char smraw[];
    uint32_t sb = smem_u32(smraw);
    const int tid = threadIdx.x;
    const int wid = tid >> 5, lane = tid & 31;
    const int g = lane >> 2, tg = lane & 3;
    const int wm = wid & 1, wn = wid >> 1;
    const int row0 = blockIdx.y * 128;
    const int col0 = blockIdx.x * 128;
    const int lr = lane & 7, lb3 = (lane >> 3) & 1, lb4 = lane >> 4;

    float c[4][4][4];
#pragma unroll
    for (int mf = 0; mf < 4; mf++)
#pragma unroll
        for (int nf = 0; nf < 4; nf++)
#pragma unroll
            for (int r = 0; r < 4; r++) c[mf][nf][r] = 0.f;

    o_load(sb, 0, row0, col0, 0, tid);
    cp_commit();
    o_load(sb, 1, row0, col0, 64, tid);
    cp_commit();

    for (int i = 0; i < 32; i++) {
        if (i + 2 < 32) cp_wait<1>();
        else            cp_wait<0>();
        __syncthreads();
        if (i + 2 < 32) {
            o_load(sb, (i + 2) % O_STG, row0, col0, (i + 2) * 64, tid);
            cp_commit();
        }
        int s = i % O_STG;
        uint32_t Ab = sb + (uint32_t)(s * A_STH) * 2;
        uint32_t Bb = sb + (uint32_t)(OOFFB + s * B_STH) * 2;
#pragma unroll
        for (int kk = 0; kk < 4; kk++) {
            uint32_t af[4][4];
#pragma unroll
            for (int mf = 0; mf < 4; mf++)
                ldsm4(af[mf], Ab + (uint32_t)((wm * 64 + mf * 16 + lb3 * 8 + lr) * PADH
                                              + kk * 16 + lb4 * 8) * 2);
#pragma unroll
            for (int np = 0; np < 2; np++) {
                uint32_t bf[4];
                ldsm4t(bf, Bb + (uint32_t)((kk * 16 + lb3 * 8 + lr) * PADB
                                           + wn * 32 + np * 16 + lb4 * 8) * 2);
#pragma unroll
                for (int mf = 0; mf < 4; mf++) {
                    mma_f16(c[mf][np * 2],     af[mf], bf[0], bf[1]);
                    mma_f16(c[mf][np * 2 + 1], af[mf], bf[2], bf[3]);
                }
            }
        }
    }

#pragma unroll
    for (int mf = 0; mf < 4; mf++) {
#pragma unroll
        for (int nf = 0; nf < 4; nf++) {
            int col = col0 + wn * 32 + nf * 8 + tg * 2;
#pragma unroll
            for (int hf = 0; hf < 2; hf++) {
                int m = row0 + wm * 64 + mf * 16 + g + hf * 8;
                *(float2*)(out + (size_t)m * DD + col) =
                    make_float2(c[mf][nf][hf * 2], c[mf][nf][hf * 2 + 1]);
            }
        }
    }
}

// ================= RoPE: fp16 in -> fp16 out, table-driven ==================
__global__ void rope_h2_kernel()
{
    int idx = blockIdx.x * blockDim.x + threadIdx.x;
    const int total = BB * HH * NN * 32;
    if (idx >= total) return;
    int hp = (idx & 31) * 2;
    int n = (idx >> 5) & (NN - 1);
    int bh = idx >> 16;

    float4 cs0 = g_cs[(size_t)n * 64 + hp];
    float4 cs1 = g_cs[(size_t)n * 64 + hp + 1];

    size_t base = ((size_t)bh * NN + n) * DHH;
    {
        __half2 a = *(const __half2*)(g_Qp + base + hp);
        __half2 b = *(const __half2*)(g_Qp + base + hp + 64);
        float q1a = __half2float(a.x), q1b = __half2float(a.y);
        float q2a = __half2float(b.x), q2b = __half2float(b.y);
        *(uint32_t*)(g_Qh + base + hp) =
            packh2((q1a * cs0.x - q2a * cs0.y) * SCALE,
                   (q1b * cs1.x - q2b * cs1.y) * SCALE);
        *(uint32_t*)(g_Qh + base + hp + 64) =
            packh2((q2a * cs0.z + q1a * cs0.w) * SCALE,
                   (q2b * cs1.z + q1b * cs1.w) * SCALE);
    }
    {
        __half2 a = *(const __half2*)(g_Kp + base + hp);
        __half2 b = *(const __half2*)(g_Kp + base + hp + 64);
        float k1a = __half2float(a.x), k1b = __half2float(a.y);
        float k2a = __half2float(b.x), k2b = __half2float(b.y);
        *(uint32_t*)(g_Kh + base + hp) =
            packh2(k1a * cs0.x - k2a * cs0.y,
                   k1b * cs1.x - k2b * cs1.y);
        *(uint32_t*)(g_Kh + base + hp + 64) =
            packh2(k2a * cs0.z + k1a * cs0.w,
                   k2b * cs1.z + k1b * cs1.w);
    }
}

// ================= Gate v4: Wg smem-staged, 4 rows per warp ================
#define GW 17
__global__ __launch_bounds__(256)
void gate4_kernel(const float* __restrict__ x,
                  const float* __restrict__ Wg,
                  const float* __restrict__ bg)
{
    __shared__ float ws[512 * GW];
    const int tid = threadIdx.x;
    const int wid = tid >> 5, lane = tid & 31;
    const int row0 = blockIdx.x * 32 + wid * 4;
    const float* xr0 = x + (size_t)row0 * DD;

    float acc[4][HH];
#pragma unroll
    for (int r = 0; r < 4; r++)
#pragma unroll
        for (int h = 0; h < HH; h++) acc[r][h] = 0.f;

    for (int c = 0; c < 4; c++) {
        __syncthreads();
#pragma unroll
        for (int j = 0; j < 8; j++) {
            int vidx = tid + j * 256;
            int kk = vidx >> 2;
            int h4 = (vidx & 3) * 4;
            float4 v = *(const float4*)(Wg + ((size_t)(c * 512 + kk) * HH + h4));
            ws[kk * GW + h4 + 0] = v.x;
            ws[kk * GW + h4 + 1] = v.y;
            ws[kk * GW + h4 + 2] = v.z;
            ws[kk * GW + h4 + 3] = v.w;
        }
        __syncthreads();
#pragma unroll
        for (int j = 0; j < 16; j++) {
            int kl = lane + j * 32;
            float xv0 = xr0[c * 512 + kl];
            float xv1 = xr0[DD + c * 512 + kl];
            float xv2 = xr0[2 * DD + c * 512 + kl];
            float xv3 = xr0[3 * DD + c * 512 + kl];
            const float* w = ws + kl * GW;
#pragma unroll
            for (int h = 0; h < HH; h++) {
                float wv = w[h];
                acc[0][h] = fmaf(xv0, wv, acc[0][h]);
                acc[1][h] = fmaf(xv1, wv, acc[1][h]);
                acc[2][h] = fmaf(xv2, wv, acc[2][h]);
                acc[3][h] = fmaf(xv3, wv, acc[3][h]);
            }
        }
    }

#pragma unroll
    for (int r = 0; r < 4; r++)
#pragma unroll
        for (int h = 0; h < HH; h++) {
#pragma unroll
            for (int off = 16; off > 0; off >>= 1)
                acc[r][h] += __shfl_xor_sync(0xffffffffu, acc[r][h], off);
        }
    if (lane == 0) {
#pragma unroll
        for (int r = 0; r < 4; r++)
#pragma unroll
            for (int h = 0; h < HH; h++)
                g_gate[(size_t)(row0 + r) * HH + h] =
                    1.f / (1.f + expf(-(acc[r][h] + bg[h])));
    }
}

// ================= Flash attention (fp16 mma, register-resident P) ==========
#define FSTR 136
#define FKV (64 * FSTR)
#define FLASH_SMEM (4 * FKV * 2)
#define NT (NN / 64)

__device__ __forceinline__ void fl_load_kv(uint32_t sb, int st,
                                           const __half* __restrict__ Kg,
                                           const __half* __restrict__ Vg,
                                           int kt, int tid)
{
    int row = tid >> 2, part = (tid & 3) * 32;
    uint32_t ks = sb + (uint32_t)(st * FKV + row * FSTR + part) * 2;
    uint32_t vs = sb + (uint32_t)((2 + st) * FKV + row * FSTR + part) * 2;
    const __half* kg = Kg + (size_t)(kt * 64 + row) * DHH + part;
    const __half* vg = Vg + (size_t)(kt * 64 + row) * DHH + part;
#pragma unroll
    for (int j = 0; j < 4; j++) {
        cp16(ks + j * 16, kg + j * 8);
        cp16(vs + j * 16, vg + j * 8);
    }
}

__global__ __launch_bounds__(256, 1)
void flash_h_kernel()
{
    extern __shared__ char smraw[];
    uint32_t sb = smem_u32(smraw);
    __half* smh = (__half*)smraw;

    const int tid = threadIdx.x;
    const int wid = tid >> 5, lane = tid & 31;
    const int g = lane >> 2, tg = lane & 3;
    const int m0 = wid * 16;
    const int qt0 = blockIdx.x * 128;
    const int bh = blockIdx.y;
    const int lr = lane & 7, lb3 = (lane >> 3) & 1, lb4 = lane >> 4;

    const __half* Qg = g_Qh + (size_t)bh * NN * DHH;
    const __half* Kg = g_Kh + (size_t)bh * NN * DHH;
    const __half* Vg = g_Vh + (size_t)bh * NN * DHH;

    uint32_t aq[8][4];
    {
        int row = tid >> 1, part = (tid & 1) * 64;
        const __half* qg = Qg + (size_t)(qt0 + row) * DHH + part;
#pragma unroll
        for (int j = 0; j < 8; j++)
            *(uint4*)(smh + row * FSTR + part + j * 8) = *(const uint4*)(qg + j * 8);
        __syncthreads();
#pragma unroll
        for (int kc = 0; kc < 8; kc++)
            ldsm4(aq[kc], sb + (uint32_t)((m0 + lb3 * 8 + lr) * FSTR + kc * 16 + lb4 * 8) * 2);
        __syncthreads();
    }

    float o[16][4];
#pragma unroll
    for (int nf = 0; nf < 16; nf++)
#pragma unroll
        for (int r = 0; r < 4; r++) o[nf][r] = 0.f;
    float mA = -1e30f, mB = -1e30f, lA = 0.f, lB = 0.f;

    fl_load_kv(sb, 0, Kg, Vg, 0, tid);
    cp_commit();

    for (int kt = 0; kt < NT; kt++) {
        int st = kt & 1;
        cp_wait<0>();
        __syncthreads();
        if (kt + 1 < NT) {
            fl_load_kv(sb, st ^ 1, Kg, Vg, kt + 1, tid);
            cp_commit();
        }
        uint32_t Kb = sb + (uint32_t)(st * FKV) * 2;
        uint32_t Vb = sb + (uint32_t)((2 + st) * FKV) * 2;

        float s[8][4];
#pragma unroll
        for (int nf = 0; nf < 8; nf++)
#pragma unroll
            for (int r = 0; r < 4; r++) s[nf][r] = 0.f;
#pragma unroll
        for (int kc = 0; kc < 8; kc++) {
#pragma unroll
            for (int np = 0; np < 4; np++) {
                uint32_t bf[4];
                ldsm4(bf, Kb + (uint32_t)((np * 16 + lb4 * 8 + lr) * FSTR
                                          + kc * 16 + lb3 * 8) * 2);
                mma_f16(s[np * 2],     aq[kc], bf[0], bf[1]);
                mma_f16(s[np * 2 + 1], aq[kc], bf[2], bf[3]);
            }
        }

        float mxA = -1e30f, mxB = -1e30f;
#pragma unroll
        for (int nf = 0; nf < 8; nf++) {
            mxA = fmaxf(mxA, fmaxf(s[nf][0], s[nf][1]));
            mxB = fmaxf(mxB, fmaxf(s[nf][2], s[nf][3]));
        }
        mxA = fmaxf(mxA, __shfl_xor_sync(0xffffffffu, mxA, 1));
        mxA = fmaxf(mxA, __shfl_xor_sync(0xffffffffu, mxA, 2));
        mxB = fmaxf(mxB, __shfl_xor_sync(0xffffffffu, mxB, 1));
        mxB = fmaxf(mxB, __shfl_xor_sync(0xffffffffu, mxB, 2));
        float mnA = fmaxf(mA, mxA), mnB = fmaxf(mB, mxB);
        float alA = __expf(mA - mnA), alB = __expf(mB - mnB);
        mA = mnA; mB = mnB;

        float smA = 0.f, smB = 0.f;
#pragma unroll
        for (int nf = 0; nf < 8; nf++) {
            s[nf][0] = __expf(s[nf][0] - mnA);
            s[nf][1] = __expf(s[nf][1] - mnA);
            s[nf][2] = __expf(s[nf][2] - mnB);
            s[nf][3] = __expf(s[nf][3] - mnB);
            smA += s[nf][0] + s[nf][1];
            smB += s[nf][2] + s[nf][3];
        }
        smA += __shfl_xor_sync(0xffffffffu, smA, 1);
        smA += __shfl_xor_sync(0xffffffffu, smA, 2);
        smB += __shfl_xor_sync(0xffffffffu, smB, 1);
        smB += __shfl_xor_sync(0xffffffffu, smB, 2);
        lA = lA * alA + smA;
        lB = lB * alB + smB;

#pragma unroll
        for (int nf = 0; nf < 16; nf++) {
            o[nf][0] *= alA; o[nf][1] *= alA;
            o[nf][2] *= alB; o[nf][3] *= alB;
        }

        uint32_t ap[4][4];
#pragma unroll
        for (int j = 0; j < 4; j++) {
            ap[j][0] = packh2(s[2 * j][0],     s[2 * j][1]);
            ap[j][1] = packh2(s[2 * j][2],     s[2 * j][3]);
            ap[j][2] = packh2(s[2 * j + 1][0], s[2 * j + 1][1]);
            ap[j][3] = packh2(s[2 * j + 1][2], s[2 * j + 1][3]);
        }

#pragma unroll
        for (int j = 0; j < 4; j++) {
#pragma unroll
            for (int nph = 0; nph < 8; nph++) {
                uint32_t bf[4];
                ldsm4t(bf, Vb + (uint32_t)((j * 16 + lb3 * 8 + lr) * FSTR
                                           + nph * 16 + lb4 * 8) * 2);
                mma_f16(o[nph * 2],     ap[j], bf[0], bf[1]);
                mma_f16(o[nph * 2 + 1], ap[j], bf[2], bf[3]);
            }
        }
    }

    const int b = bh >> 4, h = bh & 15;
    int nAr = qt0 + m0 + g, nBr = nAr + 8;
    float gA = g_gate[((size_t)(b * NN + nAr)) * HH + h];
    float gB = g_gate[((size_t)(b * NN + nBr)) * HH + h];
    float scA = gA / lA, scB = gB / lB;
    __half* dA = g_Oh + ((size_t)(b * NN + nAr) * DD + h * DHH);
    __half* dB = g_Oh + ((size_t)(b * NN + nBr) * DD + h * DHH);
#pragma unroll
    for (int nf = 0; nf < 16; nf++) {
        int dh = nf * 8 + tg * 2;
        *(uint32_t*)(dA + dh) = packh2(o[nf][0] * scA, o[nf][1] * scA);
        *(uint32_t*)(dB + dh) = packh2(o[nf][2] * scB, o[nf][3] * scB);
    }
}

// =====================================================================
extern "C" void kernel_launch(void* const* d_in, const int* in_sizes, int n_in,
                              void* d_out, int out_size)
{
    const float* x    = (const float*)d_in[0];
    const float* rope = (const float*)d_in[1];
    const float* Wq   = (const float*)d_in[2];
    const float* Wk   = (const float*)d_in[3];
    const float* Wv   = (const float*)d_in[4];
    const float* Wg   = (const float*)d_in[5];
    const float* bg   = (const float*)d_in[6];
    const float* Wo   = (const float*)d_in[7];
    float* out = (float*)d_out;

    cudaFuncSetAttribute(qkv_h_kernel,
                         cudaFuncAttributeMaxDynamicSharedMemorySize, QKV_SMEM);
    cudaFuncSetAttribute(gemm_oh_kernel,
                         cudaFuncAttributeMaxDynamicSharedMemorySize, OGEMM_SMEM);
    cudaFuncSetAttribute(flash_h_kernel,
                         cudaFuncAttributeMaxDynamicSharedMemorySize, FLASH_SMEM);

    // 0) fused conversions + cos/sin table
    {
        size_t total = XN + 4 * WN;
        conv_all_kernel<<<(int)(total / 8 / 256), 256>>>(x, Wq, Wk, Wv, Wo);
    }
    cs_table_kernel<<<(NN * 64) / 256, 256>>>(rope);

    // 1) head gates (4 rows/warp)
    gate4_kernel<<<MTOT / 32, 256>>>(x, Wg, bg);

    // 2) fused QKV projections (3-stage pipeline)
    {
        dim3 gg(DD / 128, MTOT / 128);
        qkv_h_kernel<<<gg, 256, QKV_SMEM>>>();
    }

    // 3) RoPE fp16->fp16 (table-driven)
    {
        int total = BB * HH * NN * 32;
        rope_h2_kernel<<<(total + 255) / 256, 256>>>();
    }

    // 4) flash attention
    {
        dim3 fg(NN / 128, BB * HH);
        flash_h_kernel<<<fg, 256, FLASH_SMEM>>>();
    }

    // 5) output projection (3-stage pipeline)
    {
        dim3 gg(DD / 128, MTOT / 128);
        gemm_oh_kernel<<<gg, 256, OGEMM_SMEM>>>(out);
    }
}

// round 16
// speedup vs baseline: 1.0384x; 1.0384x over previous
#include <cuda_runtime.h>
#include <cuda_fp16.h>
#include <math.h>
#include <stdint.h>

#define BB   2
#define NN   2048
#define DD   2048
#define HH   16
#define DHH  128
#define MTOT (BB*NN)
#define SCALE 0.08838834764831845f

// ---------------- device scratch ----------------
__device__ __half g_Xh [(size_t)MTOT*DD];
__device__ __half g_Wqh[(size_t)DD*DD];       // native [k][n] fp16
__device__ __half g_Wkh[(size_t)DD*DD];
__device__ __half g_Wvh[(size_t)DD*DD];
__device__ __half g_Woh[(size_t)DD*DD];
__device__ __half g_Qp [(size_t)BB*HH*NN*DHH]; // fp16 pre-rope
__device__ __half g_Kp [(size_t)BB*HH*NN*DHH];
__device__ __half g_Qh [(size_t)BB*HH*NN*DHH]; // fp16 post-rope (+scale)
__device__ __half g_Kh [(size_t)BB*HH*NN*DHH];
__device__ __half g_Vh [(size_t)BB*HH*NN*DHH];
__device__ __half g_Oh [(size_t)MTOT*DD];      // gated merged heads
__device__ float  g_gate[(size_t)MTOT*HH];
__device__ float4 g_cs [(size_t)NN*64];        // (cos1,sin1,cos2,sin2)

// ================= asm helpers =================
__device__ __forceinline__ uint32_t smem_u32(const void* p) {
    uint32_t a;
    asm("{ .reg .u64 t; cvta.to.shared.u64 t, %1; cvt.u32.u64 %0, t; }" : "=r"(a) : "l"(p));
    return a;
}
__device__ __forceinline__ void cp16(uint32_t dst, const void* src) {
    asm volatile("cp.async.cg.shared.global [%0], [%1], 16;" :: "r"(dst), "l"(src));
}
__device__ __forceinline__ void cp_commit() { asm volatile("cp.async.commit_group;" ::: "memory"); }
template<int N> __device__ __forceinline__ void cp_wait() {
    asm volatile("cp.async.wait_group %0;" :: "n"(N) : "memory");
}
__device__ __forceinline__ void ldsm4(uint32_t* r, uint32_t a) {
    asm volatile("ldmatrix.sync.aligned.m8n8.x4.shared.b16 {%0,%1,%2,%3}, [%4];"
                 : "=r"(r[0]), "=r"(r[1]), "=r"(r[2]), "=r"(r[3]) : "r"(a));
}
__device__ __forceinline__ void ldsm4t(uint32_t* r, uint32_t a) {
    asm volatile("ldmatrix.sync.aligned.m8n8.x4.trans.shared.b16 {%0,%1,%2,%3}, [%4];"
                 : "=r"(r[0]), "=r"(r[1]), "=r"(r[2]), "=r"(r[3]) : "r"(a));
}
__device__ __forceinline__ void mma_f16(float* c, const uint32_t* a, uint32_t b0, uint32_t b1) {
    asm volatile("mma.sync.aligned.m16n8k16.row.col.f32.f16.f16.f32 "
                 "{%0,%1,%2,%3}, {%4,%5,%6,%7}, {%8,%9}, {%0,%1,%2,%3};"
                 : "+f"(c[0]), "+f"(c[1]), "+f"(c[2]), "+f"(c[3])
                 : "r"(a[0]), "r"(a[1]), "r"(a[2]), "r"(a[3]), "r"(b0), "r"(b1));
}
__device__ __forceinline__ uint32_t packh2(float lo, float hi) {
    __half2 h = __floats2half2_rn(lo, hi);
    return *reinterpret_cast<uint32_t*>(&h);
}

// ================= fused conversion: x + 4 weights -> fp16 ==================
#define XN  ((size_t)MTOT*DD)
#define WN  ((size_t)DD*DD)
__global__ void conv_all_kernel(const float* __restrict__ x,
                                const float* __restrict__ Wq,
                                const float* __restrict__ Wk,
                                const float* __restrict__ Wv,
                                const float* __restrict__ Wo)
{
    size_t i = (size_t)(blockIdx.x * blockDim.x + threadIdx.x) * 8;
    const float* src; __half* dst;
    if      (i < XN)        { src = x  + i;               dst = g_Xh  + i; }
    else if (i < XN + WN)   { src = Wq + (i - XN);        dst = g_Wqh + (i - XN); }
    else if (i < XN + 2*WN) { src = Wk + (i - XN - WN);   dst = g_Wkh + (i - XN - WN); }
    else if (i < XN + 3*WN) { src = Wv + (i - XN - 2*WN); dst = g_Wvh + (i - XN - 2*WN); }
    else                    { src = Wo + (i - XN - 3*WN); dst = g_Woh + (i - XN - 3*WN); }
    float4 v0 = *(const float4*)(src);
    float4 v1 = *(const float4*)(src + 4);
    uint4 o;
    o.x = packh2(v0.x, v0.y); o.y = packh2(v0.z, v0.w);
    o.z = packh2(v1.x, v1.y); o.w = packh2(v1.z, v1.w);
    *(uint4*)(dst) = o;
}

// cos/sin table
__global__ void cs_table_kernel(const float* __restrict__ freqs)
{
    int idx = blockIdx.x * blockDim.x + threadIdx.x;
    int n = idx >> 6, half = idx & 63;
    float f1 = freqs[(size_t)n * DHH + half];
    float f2 = freqs[(size_t)n * DHH + half + 64];
    g_cs[idx] = make_float4(cosf(f1), sinf(f1), cosf(f2), sinf(f2));
}

// ================= single-weight GEMM core (fp16 mma, 2 CTAs/SM) ===========
// 128x128 tile, BK=64, 2 stages, 8 warps (2m x 4n, warp 64x32).
#define PADH 72                        // A row stride (halves)
#define PADB 136                       // B row stride (halves)
#define A_STH (128 * PADH)             // 9216 halves
#define B_STH (64 * PADB)              // 8704 halves
#define OFFB (2 * A_STH)
#define GEMM_SMEM ((2 * A_STH + 2 * B_STH) * 2)   // 71,680 B (2 CTAs/SM)

__device__ __forceinline__ void g_load(uint32_t sb, int s,
                                       const __half* __restrict__ A,
                                       const __half* __restrict__ W,
                                       int row0, int col0, int k0, int tid)
{
    {   // A: 128 rows x 64 halves
        int r = tid >> 1, hh = (tid & 1) * 32;
        uint32_t dst = sb + (uint32_t)(s * A_STH + r * PADH + hh) * 2;
        const __half* src = A + (size_t)(row0 + r) * DD + k0 + hh;
#pragma unroll
        for (int j = 0; j < 4; j++) cp16(dst + j * 16, src + j * 8);
    }
    {   // B: 64 k-rows x 128 n, native layout
        int r = tid >> 2, p = (tid & 3) * 32;
        uint32_t dst = sb + (uint32_t)(OFFB + s * B_STH + r * PADB + p) * 2;
        const __half* src = W + (size_t)(k0 + r) * DD + col0 + p;
#pragma unroll
        for (int j = 0; j < 4; j++) cp16(dst + j * 16, src + j * 8);
    }
}

// core mainloop producing c[4][4][4] for the tile
__device__ __forceinline__ void gemm_main(uint32_t sb,
                                          const __half* __restrict__ A,
                                          const __half* __restrict__ W,
                                          int row0, int col0, int tid,
                                          float c[4][4][4])
{
    const int lane = tid & 31;
    const int wid = tid >> 5;
    const int wm = wid & 1, wn = wid >> 1;
    const int lr = lane & 7, lb3 = (lane >> 3) & 1, lb4 = lane >> 4;

#pragma unroll
    for (int mf = 0; mf < 4; mf++)
#pragma unroll
        for (int nf = 0; nf < 4; nf++)
#pragma unroll
            for (int r = 0; r < 4; r++) c[mf][nf][r] = 0.f;

    g_load(sb, 0, A, W, row0, col0, 0, tid);
    cp_commit();

    for (int i = 0; i < 32; i++) {
        cp_wait<0>();
        __syncthreads();
        if (i + 1 < 32) {
            g_load(sb, (i + 1) & 1, A, W, row0, col0, (i + 1) * 64, tid);
            cp_commit();
        }
        int s = i & 1;
        uint32_t Ab = sb + (uint32_t)(s * A_STH) * 2;
        uint32_t Bb = sb + (uint32_t)(OFFB + s * B_STH) * 2;
#pragma unroll
        for (int kk = 0; kk < 4; kk++) {
            uint32_t af[4][4];
#pragma unroll
            for (int mf = 0; mf < 4; mf++)
                ldsm4(af[mf], Ab + (uint32_t)((wm * 64 + mf * 16 + lb3 * 8 + lr) * PADH
                                              + kk * 16 + lb4 * 8) * 2);
#pragma unroll
            for (int np = 0; np < 2; np++) {
                uint32_t bf[4];
                ldsm4t(bf, Bb + (uint32_t)((kk * 16 + lb3 * 8 + lr) * PADB
                                           + wn * 32 + np * 16 + lb4 * 8) * 2);
#pragma unroll
                for (int mf = 0; mf < 4; mf++) {
                    mma_f16(c[mf][np * 2],     af[mf], bf[0], bf[1]);
                    mma_f16(c[mf][np * 2 + 1], af[mf], bf[2], bf[3]);
                }
            }
        }
        __syncthreads();
    }
}

// QKV projections: gridDim.z selects weight/output; split-head fp16 store
__global__ __launch_bounds__(256, 2)
void qkv3_kernel()
{
    extern __shared__ char smraw[];
    uint32_t sb = smem_u32(smraw);
    const int tid = threadIdx.x;
    const int wid = tid >> 5, lane = tid & 31;
    const int g = lane >> 2, tg = lane & 3;
    const int wm = wid & 1, wn = wid >> 1;
    const int row0 = blockIdx.y * 128;
    const int col0 = blockIdx.x * 128;

    const __half* W = (blockIdx.z == 0) ? g_Wqh : (blockIdx.z == 1) ? g_Wkh : g_Wvh;
    __half* C = (blockIdx.z == 0) ? g_Qp : (blockIdx.z == 1) ? g_Kp : g_Vh;

    float c[4][4][4];
    gemm_main(sb, g_Xh, W, row0, col0, tid, c);

    const int h = blockIdx.x;
#pragma unroll
    for (int mf = 0; mf < 4; mf++) {
#pragma unroll
        for (int nf = 0; nf < 4; nf++) {
            int dh = wn * 32 + nf * 8 + tg * 2;
#pragma unroll
            for (int hf = 0; hf < 2; hf++) {
                int m = row0 + wm * 64 + mf * 16 + g + hf * 8;
                int b = m >> 11, n = m & (NN - 1);
                size_t off = ((size_t)(b * HH + h) * NN + n) * DHH + dh;
                *(uint32_t*)(C + off) = packh2(c[mf][nf][hf * 2], c[mf][nf][hf * 2 + 1]);
            }
        }
    }
}

// output projection: fp32 store to d_out
__global__ __launch_bounds__(256, 2)
void gemm_oh_kernel(float* __restrict__ out)
{
    extern __shared__ char smraw[];
    uint32_t sb = smem_u32(smraw);
    const int tid = threadIdx.x;
    const int wid = tid >> 5, lane = tid & 31;
    const int g = lane >> 2, tg = lane & 3;
    const int wm = wid & 1, wn = wid >> 1;
    const int row0 = blockIdx.y * 128;
    const int col0 = blockIdx.x * 128;

    float c[4][4][4];
    gemm_main(sb, g_Oh, g_Woh, row0, col0, tid, c);

#pragma unroll
    for (int mf = 0; mf < 4; mf++) {
#pragma unroll
        for (int nf = 0; nf < 4; nf++) {
            int col = col0 + wn * 32 + nf * 8 + tg * 2;
#pragma unroll
            for (int hf = 0; hf < 2; hf++) {
                int m = row0 + wm * 64 + mf * 16 + g + hf * 8;
                *(float2*)(out + (size_t)m * DD + col) =
                    make_float2(c[mf][nf][hf * 2], c[mf][nf][hf * 2 + 1]);
            }
        }
    }
}

// ================= RoPE: fp16 in -> fp16 out, table-driven ==================
__global__ void rope_h2_kernel()
{
    int idx = blockIdx.x * blockDim.x + threadIdx.x;
    const int total = BB * HH * NN * 32;
    if (idx >= total) return;
    int hp = (idx & 31) * 2;
    int n = (idx >> 5) & (NN - 1);
    int bh = idx >> 16;

    float4 cs0 = g_cs[(size_t)n * 64 + hp];
    float4 cs1 = g_cs[(size_t)n * 64 + hp + 1];

    size_t base = ((size_t)bh * NN + n) * DHH;
    {
        __half2 a = *(const __half2*)(g_Qp + base + hp);
        __half2 b = *(const __half2*)(g_Qp + base + hp + 64);
        float q1a = __half2float(a.x), q1b = __half2float(a.y);
        float q2a = __half2float(b.x), q2b = __half2float(b.y);
        *(uint32_t*)(g_Qh + base + hp) =
            packh2((q1a * cs0.x - q2a * cs0.y) * SCALE,
                   (q1b * cs1.x - q2b * cs1.y) * SCALE);
        *(uint32_t*)(g_Qh + base + hp + 64) =
            packh2((q2a * cs0.z + q1a * cs0.w) * SCALE,
                   (q2b * cs1.z + q1b * cs1.w) * SCALE);
    }
    {
        __half2 a = *(const __half2*)(g_Kp + base + hp);
        __half2 b = *(const __half2*)(g_Kp + base + hp + 64);
        float k1a = __half2float(a.x), k1b = __half2float(a.y);
        float k2a = __half2float(b.x), k2b = __half2float(b.y);
        *(uint32_t*)(g_Kh + base + hp) =
            packh2(k1a * cs0.x - k2a * cs0.y,
                   k1b * cs1.x - k2b * cs1.y);
        *(uint32_t*)(g_Kh + base + hp + 64) =
            packh2(k2a * cs0.z + k1a * cs0.w,
                   k2b * cs1.z + k1b * cs1.w);
    }
}

// ================= Gate v4: Wg smem-staged, 4 rows per warp ================
#define GW 17
__global__ __launch_bounds__(256)
void gate4_kernel(const float* __restrict__ x,
                  const float* __restrict__ Wg,
                  const float* __restrict__ bg)
{
    __shared__ float ws[512 * GW];
    const int tid = threadIdx.x;
    const int wid = tid >> 5, lane = tid & 31;
    const int row0 = blockIdx.x * 32 + wid * 4;
    const float* xr0 = x + (size_t)row0 * DD;

    float acc[4][HH];
#pragma unroll
    for (int r = 0; r < 4; r++)
#pragma unroll
        for (int h = 0; h < HH; h++) acc[r][h] = 0.f;

    for (int c = 0; c < 4; c++) {
        __syncthreads();
#pragma unroll
        for (int j = 0; j < 8; j++) {
            int vidx = tid + j * 256;
            int kk = vidx >> 2;
            int h4 = (vidx & 3) * 4;
            float4 v = *(const float4*)(Wg + ((size_t)(c * 512 + kk) * HH + h4));
            ws[kk * GW + h4 + 0] = v.x;
            ws[kk * GW + h4 + 1] = v.y;
            ws[kk * GW + h4 + 2] = v.z;
            ws[kk * GW + h4 + 3] = v.w;
        }
        __syncthreads();
#pragma unroll
        for (int j = 0; j < 16; j++) {
            int kl = lane + j * 32;
            float xv0 = xr0[c * 512 + kl];
            float xv1 = xr0[DD + c * 512 + kl];
            float xv2 = xr0[2 * DD + c * 512 + kl];
            float xv3 = xr0[3 * DD + c * 512 + kl];
            const float* w = ws + kl * GW;
#pragma unroll
            for (int h = 0; h < HH; h++) {
                float wv = w[h];
                acc[0][h] = fmaf(xv0, wv, acc[0][h]);
                acc[1][h] = fmaf(xv1, wv, acc[1][h]);
                acc[2][h] = fmaf(xv2, wv, acc[2][h]);
                acc[3][h] = fmaf(xv3, wv, acc[3][h]);
            }
        }
    }

#pragma unroll
    for (int r = 0; r < 4; r++)
#pragma unroll
        for (int h = 0; h < HH; h++) {
#pragma unroll
            for (int off = 16; off > 0; off >>= 1)
                acc[r][h] += __shfl_xor_sync(0xffffffffu, acc[r][h], off);
        }
    if (lane == 0) {
#pragma unroll
        for (int r = 0; r < 4; r++)
#pragma unroll
            for (int h = 0; h < HH; h++)
                g_gate[(size_t)(row0 + r) * HH + h] =
                    1.f / (1.f + expf(-(acc[r][h] + bg[h])));
    }
}

// ================= Flash attention (fp16 mma, register-resident P) ==========
#define FSTR 136
#define FKV (64 * FSTR)
#define FLASH_SMEM (4 * FKV * 2)
#define NT (NN / 64)

__device__ __forceinline__ void fl_load_kv(uint32_t sb, int st,
                                           const __half* __restrict__ Kg,
                                           const __half* __restrict__ Vg,
                                           int kt, int tid)
{
    int row = tid >> 2, part = (tid & 3) * 32;
    uint32_t ks = sb + (uint32_t)(st * FKV + row * FSTR + part) * 2;
    uint32_t vs = sb + (uint32_t)((2 + st) * FKV + row * FSTR + part) * 2;
    const __half* kg = Kg + (size_t)(kt * 64 + row) * DHH + part;
    const __half* vg = Vg + (size_t)(kt * 64 + row) * DHH + part;
#pragma unroll
    for (int j = 0; j < 4; j++) {
        cp16(ks + j * 16, kg + j * 8);
        cp16(vs + j * 16, vg + j * 8);
    }
}

__global__ __launch_bounds__(256, 1)
void flash_h_kernel()
{
    extern __shared__ char smraw[];
    uint32_t sb = smem_u32(smraw);
    __half* smh = (__half*)smraw;

    const int tid = threadIdx.x;
    const int wid = tid >> 5, lane = tid & 31;
    const int g = lane >> 2, tg = lane & 3;
    const int m0 = wid * 16;
    const int qt0 = blockIdx.x * 128;
    const int bh = blockIdx.y;
    const int lr = lane & 7, lb3 = (lane >> 3) & 1, lb4 = lane >> 4;

    const __half* Qg = g_Qh + (size_t)bh * NN * DHH;
    const __half* Kg = g_Kh + (size_t)bh * NN * DHH;
    const __half* Vg = g_Vh + (size_t)bh * NN * DHH;

    uint32_t aq[8][4];
    {
        int row = tid >> 1, part = (tid & 1) * 64;
        const __half* qg = Qg + (size_t)(qt0 + row) * DHH + part;
#pragma unroll
        for (int j = 0; j < 8; j++)
            *(uint4*)(smh + row * FSTR + part + j * 8) = *(const uint4*)(qg + j * 8);
        __syncthreads();
#pragma unroll
        for (int kc = 0; kc < 8; kc++)
            ldsm4(aq[kc], sb + (uint32_t)((m0 + lb3 * 8 + lr) * FSTR + kc * 16 + lb4 * 8) * 2);
        __syncthreads();
    }

    float o[16][4];
#pragma unroll
    for (int nf = 0; nf < 16; nf++)
#pragma unroll
        for (int r = 0; r < 4; r++) o[nf][r] = 0.f;
    float mA = -1e30f, mB = -1e30f, lA = 0.f, lB = 0.f;

    fl_load_kv(sb, 0, Kg, Vg, 0, tid);
    cp_commit();

    for (int kt = 0; kt < NT; kt++) {
        int st = kt & 1;
        cp_wait<0>();
        __syncthreads();
        if (kt + 1 < NT) {
            fl_load_kv(sb, st ^ 1, Kg, Vg, kt + 1, tid);
            cp_commit();
        }
        uint32_t Kb = sb + (uint32_t)(st * FKV) * 2;
        uint32_t Vb = sb + (uint32_t)((2 + st) * FKV) * 2;

        float s[8][4];
#pragma unroll
        for (int nf = 0; nf < 8; nf++)
#pragma unroll
            for (int r = 0; r < 4; r++) s[nf][r] = 0.f;
#pragma unroll
        for (int kc = 0; kc < 8; kc++) {
#pragma unroll
            for (int np = 0; np < 4; np++) {
                uint32_t bf[4];
                ldsm4(bf, Kb + (uint32_t)((np * 16 + lb4 * 8 + lr) * FSTR
                                          + kc * 16 + lb3 * 8) * 2);
                mma_f16(s[np * 2],     aq[kc], bf[0], bf[1]);
                mma_f16(s[np * 2 + 1], aq[kc], bf[2], bf[3]);
            }
        }

        float mxA = -1e30f, mxB = -1e30f;
#pragma unroll
        for (int nf = 0; nf < 8; nf++) {
            mxA = fmaxf(mxA, fmaxf(s[nf][0], s[nf][1]));
            mxB = fmaxf(mxB, fmaxf(s[nf][2], s[nf][3]));
        }
        mxA = fmaxf(mxA, __shfl_xor_sync(0xffffffffu, mxA, 1));
        mxA = fmaxf(mxA, __shfl_xor_sync(0xffffffffu, mxA, 2));
        mxB = fmaxf(mxB, __shfl_xor_sync(0xffffffffu, mxB, 1));
        mxB = fmaxf(mxB, __shfl_xor_sync(0xffffffffu, mxB, 2));
        float mnA = fmaxf(mA, mxA), mnB = fmaxf(mB, mxB);
        float alA = __expf(mA - mnA), alB = __expf(mB - mnB);
        mA = mnA; mB = mnB;

        float smA = 0.f, smB = 0.f;
#pragma unroll
        for (int nf = 0; nf < 8; nf++) {
            s[nf][0] = __expf(s[nf][0] - mnA);
            s[nf][1] = __expf(s[nf][1] - mnA);
            s[nf][2] = __expf(s[nf][2] - mnB);
            s[nf][3] = __expf(s[nf][3] - mnB);
            smA += s[nf][0] + s[nf][1];
            smB += s[nf][2] + s[nf][3];
        }
        smA += __shfl_xor_sync(0xffffffffu, smA, 1);
        smA += __shfl_xor_sync(0xffffffffu, smA, 2);
        smB += __shfl_xor_sync(0xffffffffu, smB, 1);
        smB += __shfl_xor_sync(0xffffffffu, smB, 2);
        lA = lA * alA + smA;
        lB = lB * alB + smB;

#pragma unroll
        for (int nf = 0; nf < 16; nf++) {
            o[nf][0] *= alA; o[nf][1] *= alA;
            o[nf][2] *= alB; o[nf][3] *= alB;
        }

        uint32_t ap[4][4];
#pragma unroll
        for (int j = 0; j < 4; j++) {
            ap[j][0] = packh2(s[2 * j][0],     s[2 * j][1]);
            ap[j][1] = packh2(s[2 * j][2],     s[2 * j][3]);
            ap[j][2] = packh2(s[2 * j + 1][0], s[2 * j + 1][1]);
            ap[j][3] = packh2(s[2 * j + 1][2], s[2 * j + 1][3]);
        }

#pragma unroll
        for (int j = 0; j < 4; j++) {
#pragma unroll
            for (int nph = 0; nph < 8; nph++) {
                uint32_t bf[4];
                ldsm4t(bf, Vb + (uint32_t)((j * 16 + lb3 * 8 + lr) * FSTR
                                           + nph * 16 + lb4 * 8) * 2);
                mma_f16(o[nph * 2],     ap[j], bf[0], bf[1]);
                mma_f16(o[nph * 2 + 1], ap[j], bf[2], bf[3]);
            }
        }
    }

    const int b = bh >> 4, h = bh & 15;
    int nAr = qt0 + m0 + g, nBr = nAr + 8;
    float gA = g_gate[((size_t)(b * NN + nAr)) * HH + h];
    float gB = g_gate[((size_t)(b * NN + nBr)) * HH + h];
    float scA = gA / lA, scB = gB / lB;
    __half* dA = g_Oh + ((size_t)(b * NN + nAr) * DD + h * DHH);
    __half* dB = g_Oh + ((size_t)(b * NN + nBr) * DD + h * DHH);
#pragma unroll
    for (int nf = 0; nf < 16; nf++) {
        int dh = nf * 8 + tg * 2;
        *(uint32_t*)(dA + dh) = packh2(o[nf][0] * scA, o[nf][1] * scA);
        *(uint32_t*)(dB + dh) = packh2(o[nf][2] * scB, o[nf][3] * scB);
    }
}

// =====================================================================
extern "C" void kernel_launch(void* const* d_in, const int* in_sizes, int n_in,
                              void* d_out, int out_size)
{
    const float* x    = (const float*)d_in[0];
    const float* rope = (const float*)d_in[1];
    const float* Wq   = (const float*)d_in[2];
    const float* Wk   = (const float*)d_in[3];
    const float* Wv   = (const float*)d_in[4];
    const float* Wg   = (const float*)d_in[5];
    const float* bg   = (const float*)d_in[6];
    const float* Wo   = (const float*)d_in[7];
    float* out = (float*)d_out;

    cudaFuncSetAttribute(qkv3_kernel,
                         cudaFuncAttributeMaxDynamicSharedMemorySize, GEMM_SMEM);
    cudaFuncSetAttribute(gemm_oh_kernel,
                         cudaFuncAttributeMaxDynamicSharedMemorySize, GEMM_SMEM);
    cudaFuncSetAttribute(flash_h_kernel,
                         cudaFuncAttributeMaxDynamicSharedMemorySize, FLASH_SMEM);

    // 0) fused conversions + cos/sin table
    {
        size_t total = XN + 4 * WN;
        conv_all_kernel<<<(int)(total / 8 / 256), 256>>>(x, Wq, Wk, Wv, Wo);
    }
    cs_table_kernel<<<(NN * 64) / 256, 256>>>(rope);

    // 1) head gates (4 rows/warp)
    gate4_kernel<<<MTOT / 32, 256>>>(x, Wg, bg);

    // 2) QKV projections (de-fused: 3 single-weight GEMMs, 2 CTAs/SM)
    {
        dim3 gg(DD / 128, MTOT / 128, 3);
        qkv3_kernel<<<gg, 256, GEMM_SMEM>>>();
    }

    // 3) RoPE fp16->fp16 (table-driven)
    {
        int total = BB * HH * NN * 32;
        rope_h2_kernel<<<(total + 255) / 256, 256>>>();
    }

    // 4) flash attention
    {
        dim3 fg(NN / 128, BB * HH);
        flash_h_kernel<<<fg, 256, FLASH_SMEM>>>();
    }

    // 5) output projection (2 CTAs/SM)
    {
        dim3 gg(DD / 128, MTOT / 128);
        gemm_oh_kernel<<<gg, 256, GEMM_SMEM>>>(out);
    }
}

// round 17
// speedup vs baseline: 1.1652x; 1.1221x over previous
#include <cuda_runtime.h>
#include <cuda_fp16.h>
#include <math.h>
#include <stdint.h>

#define BB   2
#define NN   2048
#define DD   2048
#define HH   16
#define DHH  128
#define MTOT (BB*NN)
#define SCALE 0.08838834764831845f

// ---------------- device scratch ----------------
__device__ __half g_Xh [(size_t)MTOT*DD];
__device__ __half g_Wqh[(size_t)DD*DD];       // native [k][n] fp16
__device__ __half g_Wkh[(size_t)DD*DD];
__device__ __half g_Wvh[(size_t)DD*DD];
__device__ __half g_Woh[(size_t)DD*DD];
__device__ __half g_Qp [(size_t)BB*HH*NN*DHH]; // fp16 pre-rope
__device__ __half g_Kp [(size_t)BB*HH*NN*DHH];
__device__ __half g_Qh [(size_t)BB*HH*NN*DHH]; // fp16 post-rope (+scale)
__device__ __half g_Kh [(size_t)BB*HH*NN*DHH];
__device__ __half g_Vh [(size_t)BB*HH*NN*DHH];
__device__ __half g_Oh [(size_t)MTOT*DD];      // gated merged heads
__device__ float  g_gate[(size_t)MTOT*HH];
__device__ float4 g_cs [(size_t)NN*64];        // (cos1,sin1,cos2,sin2)

// ================= asm helpers =================
__device__ __forceinline__ uint32_t smem_u32(const void* p) {
    uint32_t a;
    asm("{ .reg .u64 t; cvta.to.shared.u64 t, %1; cvt.u32.u64 %0, t; }" : "=r"(a) : "l"(p));
    return a;
}
__device__ __forceinline__ void cp16(uint32_t dst, const void* src) {
    asm volatile("cp.async.cg.shared.global [%0], [%1], 16;" :: "r"(dst), "l"(src));
}
__device__ __forceinline__ void cp_commit() { asm volatile("cp.async.commit_group;" ::: "memory"); }
template<int N> __device__ __forceinline__ void cp_wait() {
    asm volatile("cp.async.wait_group %0;" :: "n"(N) : "memory");
}
__device__ __forceinline__ void ldsm4(uint32_t* r, uint32_t a) {
    asm volatile("ldmatrix.sync.aligned.m8n8.x4.shared.b16 {%0,%1,%2,%3}, [%4];"
                 : "=r"(r[0]), "=r"(r[1]), "=r"(r[2]), "=r"(r[3]) : "r"(a));
}
__device__ __forceinline__ void ldsm4t(uint32_t* r, uint32_t a) {
    asm volatile("ldmatrix.sync.aligned.m8n8.x4.trans.shared.b16 {%0,%1,%2,%3}, [%4];"
                 : "=r"(r[0]), "=r"(r[1]), "=r"(r[2]), "=r"(r[3]) : "r"(a));
}
__device__ __forceinline__ void mma_f16(float* c, const uint32_t* a, uint32_t b0, uint32_t b1) {
    asm volatile("mma.sync.aligned.m16n8k16.row.col.f32.f16.f16.f32 "
                 "{%0,%1,%2,%3}, {%4,%5,%6,%7}, {%8,%9}, {%0,%1,%2,%3};"
                 : "+f"(c[0]), "+f"(c[1]), "+f"(c[2]), "+f"(c[3])
                 : "r"(a[0]), "r"(a[1]), "r"(a[2]), "r"(a[3]), "r"(b0), "r"(b1));
}
__device__ __forceinline__ uint32_t packh2(float lo, float hi) {
    __half2 h = __floats2half2_rn(lo, hi);
    return *reinterpret_cast<uint32_t*>(&h);
}

// ================= fused conversion: x + 4 weights -> fp16 ==================
#define XN  ((size_t)MTOT*DD)
#define WN  ((size_t)DD*DD)
__global__ void conv_all_kernel(const float* __restrict__ x,
                                const float* __restrict__ Wq,
                                const float* __restrict__ Wk,
                                const float* __restrict__ Wv,
                                const float* __restrict__ Wo)
{
    size_t i = (size_t)(blockIdx.x * blockDim.x + threadIdx.x) * 8;
    const float* src; __half* dst;
    if      (i < XN)        { src = x  + i;               dst = g_Xh  + i; }
    else if (i < XN + WN)   { src = Wq + (i - XN);        dst = g_Wqh + (i - XN); }
    else if (i < XN + 2*WN) { src = Wk + (i - XN - WN);   dst = g_Wkh + (i - XN - WN); }
    else if (i < XN + 3*WN) { src = Wv + (i - XN - 2*WN); dst = g_Wvh + (i - XN - 2*WN); }
    else                    { src = Wo + (i - XN - 3*WN); dst = g_Woh + (i - XN - 3*WN); }
    float4 v0 = *(const float4*)(src);
    float4 v1 = *(const float4*)(src + 4);
    uint4 o;
    o.x = packh2(v0.x, v0.y); o.y = packh2(v0.z, v0.w);
    o.z = packh2(v1.x, v1.y); o.w = packh2(v1.z, v1.w);
    *(uint4*)(dst) = o;
}

// cos/sin table
__global__ void cs_table_kernel(const float* __restrict__ freqs)
{
    int idx = blockIdx.x * blockDim.x + threadIdx.x;
    int n = idx >> 6, half = idx & 63;
    float f1 = freqs[(size_t)n * DHH + half];
    float f2 = freqs[(size_t)n * DHH + half + 64];
    g_cs[idx] = make_float4(cosf(f1), sinf(f1), cosf(f2), sinf(f2));
}

// ================= GEMM core: BK=32, 4 stages, wait<2>, 2 CTAs/SM ==========
#define PADA 40                        // A row stride (halves), 32 content
#define PADB 136                       // B row stride (halves), 128 content
#define A_ST (128 * PADA)              // 5120 halves (10,240 B)
#define B_ST (32 * PADB)               // 4352 halves (8,704 B)
#define GSTG 4
#define OFFB (GSTG * A_ST)
#define GEMM_SMEM ((GSTG * A_ST + GSTG * B_ST) * 2)   // 75,776 B
#define NCH 64                         // 2048 / 32

__device__ __forceinline__ void g_load(uint32_t sb, int s,
                                       const __half* __restrict__ A,
                                       const __half* __restrict__ W,
                                       int row0, int col0, int k0, int tid)
{
    {   // A: 128 rows x 32 halves (2 cp16/thread)
        int r = tid >> 1, hh = (tid & 1) * 16;
        uint32_t dst = sb + (uint32_t)(s * A_ST + r * PADA + hh) * 2;
        const __half* src = A + (size_t)(row0 + r) * DD + k0 + hh;
        cp16(dst, src); cp16(dst + 16, src + 8);
    }
    {   // B: 32 k-rows x 128 n (2 cp16/thread), native layout
        int r = tid >> 3, p = (tid & 7) * 16;
        uint32_t dst = sb + (uint32_t)(OFFB + s * B_ST + r * PADB + p) * 2;
        const __half* src = W + (size_t)(k0 + r) * DD + col0 + p;
        cp16(dst, src); cp16(dst + 16, src + 8);
    }
}

__device__ __forceinline__ void gemm_main(uint32_t sb,
                                          const __half* __restrict__ A,
                                          const __half* __restrict__ W,
                                          int row0, int col0, int tid,
                                          float c[4][4][4])
{
    const int lane = tid & 31;
    const int wid = tid >> 5;
    const int wm = wid & 1, wn = wid >> 1;
    const int lr = lane & 7, lb3 = (lane >> 3) & 1, lb4 = lane >> 4;

#pragma unroll
    for (int mf = 0; mf < 4; mf++)
#pragma unroll
        for (int nf = 0; nf < 4; nf++)
#pragma unroll
            for (int r = 0; r < 4; r++) c[mf][nf][r] = 0.f;

    g_load(sb, 0, A, W, row0, col0, 0, tid);
    cp_commit();
    g_load(sb, 1, A, W, row0, col0, 32, tid);
    cp_commit();
    g_load(sb, 2, A, W, row0, col0, 64, tid);
    cp_commit();

    for (int i = 0; i < NCH; i++) {
        if (i <= NCH - 3)      cp_wait<2>();
        else if (i == NCH - 2) cp_wait<1>();
        else                   cp_wait<0>();
        __syncthreads();
        if (i + 3 < NCH) {
            g_load(sb, (i + 3) & 3, A, W, row0, col0, (i + 3) * 32, tid);
            cp_commit();
        }
        int s = i & 3;
        uint32_t Ab = sb + (uint32_t)(s * A_ST) * 2;
        uint32_t Bb = sb + (uint32_t)(OFFB + s * B_ST) * 2;
#pragma unroll
        for (int kk = 0; kk < 2; kk++) {
            uint32_t af[4][4];
#pragma unroll
            for (int mf = 0; mf < 4; mf++)
                ldsm4(af[mf], Ab + (uint32_t)((wm * 64 + mf * 16 + lb3 * 8 + lr) * PADA
                                              + kk * 16 + lb4 * 8) * 2);
#pragma unroll
            for (int np = 0; np < 2; np++) {
                uint32_t bf[4];
                ldsm4t(bf, Bb + (uint32_t)((kk * 16 + lb3 * 8 + lr) * PADB
                                           + wn * 32 + np * 16 + lb4 * 8) * 2);
#pragma unroll
                for (int mf = 0; mf < 4; mf++) {
                    mma_f16(c[mf][np * 2],     af[mf], bf[0], bf[1]);
                    mma_f16(c[mf][np * 2 + 1], af[mf], bf[2], bf[3]);
                }
            }
        }
    }
}

// QKV projections: gridDim.z selects weight/output; split-head fp16 store
__global__ __launch_bounds__(256, 2)
void qkv3_kernel()
{
    extern __shared__ char smraw[];
    uint32_t sb = smem_u32(smraw);
    const int tid = threadIdx.x;
    const int wid = tid >> 5, lane = tid & 31;
    const int g = lane >> 2, tg = lane & 3;
    const int wm = wid & 1, wn = wid >> 1;
    const int row0 = blockIdx.y * 128;
    const int col0 = blockIdx.x * 128;

    const __half* W = (blockIdx.z == 0) ? g_Wqh : (blockIdx.z == 1) ? g_Wkh : g_Wvh;
    __half* C = (blockIdx.z == 0) ? g_Qp : (blockIdx.z == 1) ? g_Kp : g_Vh;

    float c[4][4][4];
    gemm_main(sb, g_Xh, W, row0, col0, tid, c);

    const int h = blockIdx.x;
#pragma unroll
    for (int mf = 0; mf < 4; mf++) {
#pragma unroll
        for (int nf = 0; nf < 4; nf++) {
            int dh = wn * 32 + nf * 8 + tg * 2;
#pragma unroll
            for (int hf = 0; hf < 2; hf++) {
                int m = row0 + wm * 64 + mf * 16 + g + hf * 8;
                int b = m >> 11, n = m & (NN - 1);
                size_t off = ((size_t)(b * HH + h) * NN + n) * DHH + dh;
                *(uint32_t*)(C + off) = packh2(c[mf][nf][hf * 2], c[mf][nf][hf * 2 + 1]);
            }
        }
    }
}

// output projection: fp32 store to d_out
__global__ __launch_bounds__(256, 2)
void gemm_oh_kernel(float* __restrict__ out)
{
    extern __shared__ char smraw[];
    uint32_t sb = smem_u32(smraw);
    const int tid = threadIdx.x;
    const int wid = tid >> 5, lane = tid & 31;
    const int g = lane >> 2, tg = lane & 3;
    const int wm = wid & 1, wn = wid >> 1;
    const int row0 = blockIdx.y * 128;
    const int col0 = blockIdx.x * 128;

    float c[4][4][4];
    gemm_main(sb, g_Oh, g_Woh, row0, col0, tid, c);

#pragma unroll
    for (int mf = 0; mf < 4; mf++) {
#pragma unroll
        for (int nf = 0; nf < 4; nf++) {
            int col = col0 + wn * 32 + nf * 8 + tg * 2;
#pragma unroll
            for (int hf = 0; hf < 2; hf++) {
                int m = row0 + wm * 64 + mf * 16 + g + hf * 8;
                *(float2*)(out + (size_t)m * DD + col) =
                    make_float2(c[mf][nf][hf * 2], c[mf][nf][hf * 2 + 1]);
            }
        }
    }
}

// ================= RoPE: fp16 in -> fp16 out, table-driven ==================
__global__ void rope_h2_kernel()
{
    int idx = blockIdx.x * blockDim.x + threadIdx.x;
    const int total = BB * HH * NN * 32;
    if (idx >= total) return;
    int hp = (idx & 31) * 2;
    int n = (idx >> 5) & (NN - 1);
    int bh = idx >> 16;

    float4 cs0 = g_cs[(size_t)n * 64 + hp];
    float4 cs1 = g_cs[(size_t)n * 64 + hp + 1];

    size_t base = ((size_t)bh * NN + n) * DHH;
    {
        __half2 a = *(const __half2*)(g_Qp + base + hp);
        __half2 b = *(const __half2*)(g_Qp + base + hp + 64);
        float q1a = __half2float(a.x), q1b = __half2float(a.y);
        float q2a = __half2float(b.x), q2b = __half2float(b.y);
        *(uint32_t*)(g_Qh + base + hp) =
            packh2((q1a * cs0.x - q2a * cs0.y) * SCALE,
                   (q1b * cs1.x - q2b * cs1.y) * SCALE);
        *(uint32_t*)(g_Qh + base + hp + 64) =
            packh2((q2a * cs0.z + q1a * cs0.w) * SCALE,
                   (q2b * cs1.z + q1b * cs1.w) * SCALE);
    }
    {
        __half2 a = *(const __half2*)(g_Kp + base + hp);
        __half2 b = *(const __half2*)(g_Kp + base + hp + 64);
        float k1a = __half2float(a.x), k1b = __half2float(a.y);
        float k2a = __half2float(b.x), k2b = __half2float(b.y);
        *(uint32_t*)(g_Kh + base + hp) =
            packh2(k1a * cs0.x - k2a * cs0.y,
                   k1b * cs1.x - k2b * cs1.y);
        *(uint32_t*)(g_Kh + base + hp + 64) =
            packh2(k2a * cs0.z + k1a * cs0.w,
                   k2b * cs1.z + k1b * cs1.w);
    }
}

// ================= Gate v4: Wg smem-staged, 4 rows per warp ================
#define GW 17
__global__ __launch_bounds__(256)
void gate4_kernel(const float* __restrict__ x,
                  const float* __restrict__ Wg,
                  const float* __restrict__ bg)
{
    __shared__ float ws[512 * GW];
    const int tid = threadIdx.x;
    const int wid = tid >> 5, lane = tid & 31;
    const int row0 = blockIdx.x * 32 + wid * 4;
    const float* xr0 = x + (size_t)row0 * DD;

    float acc[4][HH];
#pragma unroll
    for (int r = 0; r < 4; r++)
#pragma unroll
        for (int h = 0; h < HH; h++) acc[r][h] = 0.f;

    for (int c = 0; c < 4; c++) {
        __syncthreads();
#pragma unroll
        for (int j = 0; j < 8; j++) {
            int vidx = tid + j * 256;
            int kk = vidx >> 2;
            int h4 = (vidx & 3) * 4;
            float4 v = *(const float4*)(Wg + ((size_t)(c * 512 + kk) * HH + h4));
            ws[kk * GW + h4 + 0] = v.x;
            ws[kk * GW + h4 + 1] = v.y;
            ws[kk * GW + h4 + 2] = v.z;
            ws[kk * GW + h4 + 3] = v.w;
        }
        __syncthreads();
#pragma unroll
        for (int j = 0; j < 16; j++) {
            int kl = lane + j * 32;
            float xv0 = xr0[c * 512 + kl];
            float xv1 = xr0[DD + c * 512 + kl];
            float xv2 = xr0[2 * DD + c * 512 + kl];
            float xv3 = xr0[3 * DD + c * 512 + kl];
            const float* w = ws + kl * GW;
#pragma unroll
            for (int h = 0; h < HH; h++) {
                float wv = w[h];
                acc[0][h] = fmaf(xv0, wv, acc[0][h]);
                acc[1][h] = fmaf(xv1, wv, acc[1][h]);
                acc[2][h] = fmaf(xv2, wv, acc[2][h]);
                acc[3][h] = fmaf(xv3, wv, acc[3][h]);
            }
        }
    }

#pragma unroll
    for (int r = 0; r < 4; r++)
#pragma unroll
        for (int h = 0; h < HH; h++) {
#pragma unroll
            for (int off = 16; off > 0; off >>= 1)
                acc[r][h] += __shfl_xor_sync(0xffffffffu, acc[r][h], off);
        }
    if (lane == 0) {
#pragma unroll
        for (int r = 0; r < 4; r++)
#pragma unroll
            for (int h = 0; h < HH; h++)
                g_gate[(size_t)(row0 + r) * HH + h] =
                    1.f / (1.f + expf(-(acc[r][h] + bg[h])));
    }
}

// ================= Flash attention (fp16 mma, register-resident P) ==========
#define FSTR 136
#define FKV (64 * FSTR)
#define FLASH_SMEM (4 * FKV * 2)
#define NT (NN / 64)

__device__ __forceinline__ void fl_load_kv(uint32_t sb, int st,
                                           const __half* __restrict__ Kg,
                                           const __half* __restrict__ Vg,
                                           int kt, int tid)
{
    int row = tid >> 2, part = (tid & 3) * 32;
    uint32_t ks = sb + (uint32_t)(st * FKV + row * FSTR + part) * 2;
    uint32_t vs = sb + (uint32_t)((2 + st) * FKV + row * FSTR + part) * 2;
    const __half* kg = Kg + (size_t)(kt * 64 + row) * DHH + part;
    const __half* vg = Vg + (size_t)(kt * 64 + row) * DHH + part;
#pragma unroll
    for (int j = 0; j < 4; j++) {
        cp16(ks + j * 16, kg + j * 8);
        cp16(vs + j * 16, vg + j * 8);
    }
}

__global__ __launch_bounds__(256, 1)
void flash_h_kernel()
{
    extern __shared__ char smraw[];
    uint32_t sb = smem_u32(smraw);
    __half* smh = (__half*)smraw;

    const int tid = threadIdx.x;
    const int wid = tid >> 5, lane = tid & 31;
    const int g = lane >> 2, tg = lane & 3;
    const int m0 = wid * 16;
    const int qt0 = blockIdx.x * 128;
    const int bh = blockIdx.y;
    const int lr = lane & 7, lb3 = (lane >> 3) & 1, lb4 = lane >> 4;

    const __half* Qg = g_Qh + (size_t)bh * NN * DHH;
    const __half* Kg = g_Kh + (size_t)bh * NN * DHH;
    const __half* Vg = g_Vh + (size_t)bh * NN * DHH;

    uint32_t aq[8][4];
    {
        int row = tid >> 1, part = (tid & 1) * 64;
        const __half* qg = Qg + (size_t)(qt0 + row) * DHH + part;
#pragma unroll
        for (int j = 0; j < 8; j++)
            *(uint4*)(smh + row * FSTR + part + j * 8) = *(const uint4*)(qg + j * 8);
        __syncthreads();
#pragma unroll
        for (int kc = 0; kc < 8; kc++)
            ldsm4(aq[kc], sb + (uint32_t)((m0 + lb3 * 8 + lr) * FSTR + kc * 16 + lb4 * 8) * 2);
        __syncthreads();
    }

    float o[16][4];
#pragma unroll
    for (int nf = 0; nf < 16; nf++)
#pragma unroll
        for (int r = 0; r < 4; r++) o[nf][r] = 0.f;
    float mA = -1e30f, mB = -1e30f, lA = 0.f, lB = 0.f;

    fl_load_kv(sb, 0, Kg, Vg, 0, tid);
    cp_commit();

    for (int kt = 0; kt < NT; kt++) {
        int st = kt & 1;
        cp_wait<0>();
        __syncthreads();
        if (kt + 1 < NT) {
            fl_load_kv(sb, st ^ 1, Kg, Vg, kt + 1, tid);
            cp_commit();
        }
        uint32_t Kb = sb + (uint32_t)(st * FKV) * 2;
        uint32_t Vb = sb + (uint32_t)((2 + st) * FKV) * 2;

        float s[8][4];
#pragma unroll
        for (int nf = 0; nf < 8; nf++)
#pragma unroll
            for (int r = 0; r < 4; r++) s[nf][r] = 0.f;
#pragma unroll
        for (int kc = 0; kc < 8; kc++) {
#pragma unroll
            for (int np = 0; np < 4; np++) {
                uint32_t bf[4];
                ldsm4(bf, Kb + (uint32_t)((np * 16 + lb4 * 8 + lr) * FSTR
                                          + kc * 16 + lb3 * 8) * 2);
                mma_f16(s[np * 2],     aq[kc], bf[0], bf[1]);
                mma_f16(s[np * 2 + 1], aq[kc], bf[2], bf[3]);
            }
        }

        float mxA = -1e30f, mxB = -1e30f;
#pragma unroll
        for (int nf = 0; nf < 8; nf++) {
            mxA = fmaxf(mxA, fmaxf(s[nf][0], s[nf][1]));
            mxB = fmaxf(mxB, fmaxf(s[nf][2], s[nf][3]));
        }
        mxA = fmaxf(mxA, __shfl_xor_sync(0xffffffffu, mxA, 1));
        mxA = fmaxf(mxA, __shfl_xor_sync(0xffffffffu, mxA, 2));
        mxB = fmaxf(mxB, __shfl_xor_sync(0xffffffffu, mxB, 1));
        mxB = fmaxf(mxB, __shfl_xor_sync(0xffffffffu, mxB, 2));
        float mnA = fmaxf(mA, mxA), mnB = fmaxf(mB, mxB);
        float alA = __expf(mA - mnA), alB = __expf(mB - mnB);
        mA = mnA; mB = mnB;

        float smA = 0.f, smB = 0.f;
#pragma unroll
        for (int nf = 0; nf < 8; nf++) {
            s[nf][0] = __expf(s[nf][0] - mnA);
            s[nf][1] = __expf(s[nf][1] - mnA);
            s[nf][2] = __expf(s[nf][2] - mnB);
            s[nf][3] = __expf(s[nf][3] - mnB);
            smA += s[nf][0] + s[nf][1];
            smB += s[nf][2] + s[nf][3];
        }
        smA += __shfl_xor_sync(0xffffffffu, smA, 1);
        smA += __shfl_xor_sync(0xffffffffu, smA, 2);
        smB += __shfl_xor_sync(0xffffffffu, smB, 1);
        smB += __shfl_xor_sync(0xffffffffu, smB, 2);
        lA = lA * alA + smA;
        lB = lB * alB + smB;

#pragma unroll
        for (int nf = 0; nf < 16; nf++) {
            o[nf][0] *= alA; o[nf][1] *= alA;
            o[nf][2] *= alB; o[nf][3] *= alB;
        }

        uint32_t ap[4][4];
#pragma unroll
        for (int j = 0; j < 4; j++) {
            ap[j][0] = packh2(s[2 * j][0],     s[2 * j][1]);
            ap[j][1] = packh2(s[2 * j][2],     s[2 * j][3]);
            ap[j][2] = packh2(s[2 * j + 1][0], s[2 * j + 1][1]);
            ap[j][3] = packh2(s[2 * j + 1][2], s[2 * j + 1][3]);
        }

#pragma unroll
        for (int j = 0; j < 4; j++) {
#pragma unroll
            for (int nph = 0; nph < 8; nph++) {
                uint32_t bf[4];
                ldsm4t(bf, Vb + (uint32_t)((j * 16 + lb3 * 8 + lr) * FSTR
                                           + nph * 16 + lb4 * 8) * 2);
                mma_f16(o[nph * 2],     ap[j], bf[0], bf[1]);
                mma_f16(o[nph * 2 + 1], ap[j], bf[2], bf[3]);
            }
        }
    }

    const int b = bh >> 4, h = bh & 15;
    int nAr = qt0 + m0 + g, nBr = nAr + 8;
    float gA = g_gate[((size_t)(b * NN + nAr)) * HH + h];
    float gB = g_gate[((size_t)(b * NN + nBr)) * HH + h];
    float scA = gA / lA, scB = gB / lB;
    __half* dA = g_Oh + ((size_t)(b * NN + nAr) * DD + h * DHH);
    __half* dB = g_Oh + ((size_t)(b * NN + nBr) * DD + h * DHH);
#pragma unroll
    for (int nf = 0; nf < 16; nf++) {
        int dh = nf * 8 + tg * 2;
        *(uint32_t*)(dA + dh) = packh2(o[nf][0] * scA, o[nf][1] * scA);
        *(uint32_t*)(dB + dh) = packh2(o[nf][2] * scB, o[nf][3] * scB);
    }
}

// =====================================================================
extern "C" void kernel_launch(void* const* d_in, const int* in_sizes, int n_in,
                              void* d_out, int out_size)
{
    const float* x    = (const float*)d_in[0];
    const float* rope = (const float*)d_in[1];
    const float* Wq   = (const float*)d_in[2];
    const float* Wk   = (const float*)d_in[3];
    const float* Wv   = (const float*)d_in[4];
    const float* Wg   = (const float*)d_in[5];
    const float* bg   = (const float*)d_in[6];
    const float* Wo   = (const float*)d_in[7];
    float* out = (float*)d_out;

    cudaFuncSetAttribute(qkv3_kernel,
                         cudaFuncAttributeMaxDynamicSharedMemorySize, GEMM_SMEM);
    cudaFuncSetAttribute(gemm_oh_kernel,
                         cudaFuncAttributeMaxDynamicSharedMemorySize, GEMM_SMEM);
    cudaFuncSetAttribute(flash_h_kernel,
                         cudaFuncAttributeMaxDynamicSharedMemorySize, FLASH_SMEM);

    // 0) fused conversions + cos/sin table
    {
        size_t total = XN + 4 * WN;
        conv_all_kernel<<<(int)(total / 8 / 256), 256>>>(x, Wq, Wk, Wv, Wo);
    }
    cs_table_kernel<<<(NN * 64) / 256, 256>>>(rope);

    // 1) head gates (4 rows/warp)
    gate4_kernel<<<MTOT / 32, 256>>>(x, Wg, bg);

    // 2) QKV projections (BK=32, 4-stage pipeline, 2 CTAs/SM)
    {
        dim3 gg(DD / 128, MTOT / 128, 3);
        qkv3_kernel<<<gg, 256, GEMM_SMEM>>>();
    }

    // 3) RoPE fp16->fp16 (table-driven)
    {
        int total = BB * HH * NN * 32;
        rope_h2_kernel<<<(total + 255) / 256, 256>>>();
    }

    // 4) flash attention
    {
        dim3 fg(NN / 128, BB * HH);
        flash_h_kernel<<<fg, 256, FLASH_SMEM>>>();
    }

    // 5) output projection (BK=32, 4-stage pipeline, 2 CTAs/SM)
    {
        dim3 gg(DD / 128, MTOT / 128);
        gemm_oh_kernel<<<gg, 256, GEMM_SMEM>>>(out);
    }
}